// round 1
// baseline (speedup 1.0000x reference)
#include <cuda_runtime.h>
#include <stdint.h>

// Shapes (capacities; runtime sizes derived from in_sizes)
#define NMAX 65536
#define EMAX 2100000
#define H 64

// ---------------- scratch (device globals: no allocation allowed) ----------
__device__ float g_deg[NMAX];
__device__ float g_dis[NMAX];
__device__ float g_norm[EMAX];
__device__ __align__(16) float g_xw[NMAX * H];
__device__ __align__(16) float g_agg[NMAX * H];
__device__ float g_logits[NMAX];
__device__ unsigned g_maxbits;
__device__ float g_sum;

// ---------------- helpers ---------------------------------------------------
__device__ __forceinline__ float sigmoidf_(float x) {
    return 1.0f / (1.0f + __expf(-x));
}

__device__ __forceinline__ void red_add_v4(float* addr, float4 v) {
    asm volatile("red.global.add.v4.f32 [%0], {%1, %2, %3, %4};"
                 :: "l"(addr), "f"(v.x), "f"(v.y), "f"(v.z), "f"(v.w)
                 : "memory");
}

// monotonic float<->uint mapping for atomicMax over signed floats
__device__ __forceinline__ unsigned f2key(float f) {
    unsigned b = __float_as_uint(f);
    return (b & 0x80000000u) ? ~b : (b | 0x80000000u);
}
__device__ __forceinline__ float key2f(unsigned k) {
    unsigned b = (k & 0x80000000u) ? (k & 0x7fffffffu) : ~k;
    return __uint_as_float(b);
}

// ---------------- kernels ---------------------------------------------------
__global__ void k_reset() {
    g_maxbits = 0u;   // maps to -inf
    g_sum = 0.0f;
}

__global__ void k_deg_init(int n) {
    int i = blockIdx.x * blockDim.x + threadIdx.x;
    if (i < n) g_deg[i] = 1.0f;   // self-loop weight
}

__global__ void k_deg_acc(const int* __restrict__ col,
                          const float* __restrict__ w, int E) {
    int e = blockIdx.x * blockDim.x + threadIdx.x;
    if (e < E) atomicAdd(&g_deg[col[e]], w[e]);
}

__global__ void k_dis(int n) {
    int i = blockIdx.x * blockDim.x + threadIdx.x;
    if (i < n) {
        float d = g_deg[i];
        g_dis[i] = (d > 0.0f) ? rsqrtf(d) : 0.0f;
    }
}

__global__ void k_norm(const int* __restrict__ row, const int* __restrict__ col,
                       const float* __restrict__ w, int E) {
    int e = blockIdx.x * blockDim.x + threadIdx.x;
    if (e < E) g_norm[e] = g_dis[row[e]] * w[e] * g_dis[col[e]];
}

// Layer 1: xw = x @ W1 (F x 64); agg = dis^2 * xw (self-loop term)
__global__ void k_xw1(const float* __restrict__ x, const float* __restrict__ W1,
                      int n, int F) {
    __shared__ float W1s[16 * H];   // F <= 16
    for (int idx = threadIdx.x; idx < F * H; idx += blockDim.x)
        W1s[idx] = W1[idx];
    __syncthreads();
    int i = blockIdx.x * 4 + (threadIdx.x >> 6);
    int h = threadIdx.x & 63;
    if (i >= n) return;
    const float* xr = x + (size_t)i * F;
    float acc = 0.0f;
    for (int k = 0; k < F; k++) acc = fmaf(xr[k], W1s[k * H + h], acc);
    g_xw[i * H + h] = acc;
    float d = g_dis[i];
    g_agg[i * H + h] = d * d * acc;
}

// Edge aggregation: agg[col] += norm * xw[row]; 16 threads/edge, float4 each.
__global__ void k_edge(const int* __restrict__ row, const int* __restrict__ col,
                       int E) {
    int gid = blockIdx.x * blockDim.x + threadIdx.x;
    int e = gid >> 4;
    int t = gid & 15;
    if (e >= E) return;
    int r = __ldg(&row[e]);
    int c = __ldg(&col[e]);
    float nm = __ldg(&g_norm[e]);
    float4 v = *reinterpret_cast<const float4*>(&g_xw[r * H + t * 4]);
    v.x *= nm; v.y *= nm; v.z *= nm; v.w *= nm;
    red_add_v4(&g_agg[c * H + t * 4], v);
}

// Fused: h = sigmoid(agg + b_prev); xw = h @ W (64x64); agg = dis^2 * xw
// Block: 256 threads, 32 nodes per block.
__global__ void k_layer(const float* __restrict__ W, const float* __restrict__ bprev,
                        int n) {
    __shared__ float Ws[H * (H + 1)];   // padded: Ws[k*65+h]
    __shared__ float hs[32 * H];
    int tid = threadIdx.x;
    for (int idx = tid; idx < H * H; idx += 256) {
        int k = idx >> 6, h = idx & 63;
        Ws[k * (H + 1) + h] = W[idx];
    }
    int base = blockIdx.x * 32;
    #pragma unroll
    for (int r = 0; r < 8; r++) {
        int idx = r * 256 + tid;
        int node = idx >> 6, h = idx & 63;
        int gi = base + node;
        float v = 0.0f;
        if (gi < n) v = sigmoidf_(g_agg[gi * H + h] + bprev[h]);
        hs[idx] = v;
    }
    __syncthreads();

    int h = tid & 63;
    int ng = tid >> 6;   // node group 0..3, 8 nodes each
    float acc[8];
    #pragma unroll
    for (int r = 0; r < 8; r++) acc[r] = 0.0f;
    #pragma unroll 4
    for (int k = 0; k < H; k++) {
        float wk = Ws[k * (H + 1) + h];
        #pragma unroll
        for (int r = 0; r < 8; r++)
            acc[r] = fmaf(hs[(ng * 8 + r) * H + k], wk, acc[r]);
    }
    #pragma unroll
    for (int r = 0; r < 8; r++) {
        int i = base + ng * 8 + r;
        if (i < n) {
            g_xw[i * H + h] = acc[r];
            float d = g_dis[i];
            g_agg[i * H + h] = d * d * acc[r];
        }
    }
}

// Final head: h3 = sigmoid(agg + b3); logits = h3 @ Wl + bl; track global max.
__global__ void k_final(const float* __restrict__ Wl, const float* __restrict__ bl,
                        const float* __restrict__ b3, int n) {
    __shared__ unsigned smax[8];
    int lane = threadIdx.x & 31;
    int warp = threadIdx.x >> 5;
    int i = blockIdx.x * 8 + warp;
    unsigned key = 0u;
    if (i < n) {
        float v1 = sigmoidf_(g_agg[i * H + lane] + b3[lane]);
        float v2 = sigmoidf_(g_agg[i * H + 32 + lane] + b3[32 + lane]);
        float p = fmaf(v1, Wl[lane], v2 * Wl[32 + lane]);
        #pragma unroll
        for (int o = 16; o > 0; o >>= 1) p += __shfl_xor_sync(0xffffffffu, p, o);
        if (lane == 0) {
            float lg = p + bl[0];
            g_logits[i] = lg;
            key = f2key(lg);
        }
    }
    if (lane == 0) smax[warp] = key;
    __syncthreads();
    if (threadIdx.x == 0) {
        unsigned m = smax[0];
        #pragma unroll
        for (int w = 1; w < 8; w++) m = max(m, smax[w]);
        if (m) atomicMax(&g_maxbits, m);
    }
}

__global__ void k_expsum(float* __restrict__ out, int n) {
    __shared__ float ssum[8];
    int i = blockIdx.x * blockDim.x + threadIdx.x;
    float mx = key2f(g_maxbits);
    float e = 0.0f;
    if (i < n) {
        e = expf(g_logits[i] - mx);
        out[i] = e;
    }
    #pragma unroll
    for (int o = 16; o > 0; o >>= 1) e += __shfl_xor_sync(0xffffffffu, e, o);
    int lane = threadIdx.x & 31, warp = threadIdx.x >> 5;
    if (lane == 0) ssum[warp] = e;
    __syncthreads();
    if (threadIdx.x == 0) {
        float s = 0.0f;
        #pragma unroll
        for (int w = 0; w < 8; w++) s += ssum[w];
        atomicAdd(&g_sum, s);
    }
}

__global__ void k_scale(float* __restrict__ out, int n) {
    int i = blockIdx.x * blockDim.x + threadIdx.x;
    if (i < n) out[i] *= (1.0f / g_sum);
}

// ---------------- launch -----------------------------------------------------
extern "C" void kernel_launch(void* const* d_in, const int* in_sizes, int n_in,
                              void* d_out, int out_size) {
    const float* x   = (const float*)d_in[0];
    const int*   edg = (const int*)d_in[1];     // [2, E] int32
    const float* w   = (const float*)d_in[2];
    const float* W1  = (const float*)d_in[3];
    const float* b1  = (const float*)d_in[4];
    const float* W2  = (const float*)d_in[5];
    const float* b2  = (const float*)d_in[6];
    const float* W3  = (const float*)d_in[7];
    const float* b3  = (const float*)d_in[8];
    const float* Wl  = (const float*)d_in[9];
    const float* bl  = (const float*)d_in[10];
    float* out = (float*)d_out;

    int E = in_sizes[2];                 // weights: one per edge
    int F = in_sizes[3] / H;             // W1: [F, 64]
    int n = in_sizes[0] / F;

    const int* row = edg;
    const int* col = edg + E;

    int nb_n  = (n + 255) / 256;
    int nb_e  = (E + 255) / 256;
    int nb_e16 = (E * 16 + 255) / 256;   // fits in int for E <= 2.1M... (33.6M ok)

    k_reset<<<1, 1>>>();
    k_deg_init<<<nb_n, 256>>>(n);
    k_deg_acc<<<nb_e, 256>>>(col, w, E);
    k_dis<<<nb_n, 256>>>(n);
    k_norm<<<nb_e, 256>>>(row, col, w, E);

    // layer 1
    k_xw1<<<(n + 3) / 4, 256>>>(x, W1, n, F);
    k_edge<<<nb_e16, 256>>>(row, col, E);
    // layer 2 (sigmoid(.+b1) fused into load)
    k_layer<<<(n + 31) / 32, 256>>>(W2, b1, n);
    k_edge<<<nb_e16, 256>>>(row, col, E);
    // layer 3
    k_layer<<<(n + 31) / 32, 256>>>(W3, b2, n);
    k_edge<<<nb_e16, 256>>>(row, col, E);

    // head + softmax over nodes
    k_final<<<(n + 7) / 8, 256>>>(Wl, bl, b3, n);
    k_expsum<<<nb_n, 256>>>(out, n);
    k_scale<<<nb_n, 256>>>(out, n);
}